// round 11
// baseline (speedup 1.0000x reference)
#include <cuda_runtime.h>
#include <math.h>

#define NPROP 8192
#define NC 81
#define NFG 80
#define NDET 100
#define SCORE_T 0.05f
#define NMS_T 0.5f
#define BBOX_CLIP 4.135166556742356f   // log(1000/16)
#define CAP 384                         // max survivors/class (E[M]~235, ~10 sigma)
#define NW64 6                          // 64-bit mask words per row
#define NW32 12                         // 32-bit words per row
#define TN 256
#define SPLIT 4                         // mask CTAs per class
#define FULLM 0xffffffffu
#define MASK_WORDS (NFG * CAP * NW32)   // 368640

// Scratch (no cudaMalloc)
__device__ int      g_count[NFG];       // zero at load; K3 resets post-read
__device__ int      g_cn[NFG * NPROP];
__device__ float    g_cs[NFG * NPROP];
__device__ unsigned g_mask[MASK_WORDS]; // zeroed by K1 each run

// ---------------------------------------------------------------------------
// Kernel 1: softmax + threshold push (8 lanes/proposal, smem-staged logits)
//           + zero g_mask for this run.
// ---------------------------------------------------------------------------
#define SM_PROPS 32
__global__ void __launch_bounds__(256, 1)
softmax_kernel(const float* __restrict__ logits) {
    __shared__ float slog[SM_PROPS * NC];          // 10368 B
    const int tid = threadIdx.x;
    const int gid = blockIdx.x * 256 + tid;        // 0..65535

    const float4* src = (const float4*)(logits + (size_t)blockIdx.x * SM_PROPS * NC);
    float4* dst = (float4*)slog;
    #pragma unroll
    for (int k = 0; k < 3; k++) {
        int idx = tid + k * 256;
        if (idx < (SM_PROPS * NC) / 4) dst[idx] = src[idx];
    }

    // zero this run's suppression mask (independent of staging)
    for (int w = gid; w < MASK_WORDS; w += 65536) g_mask[w] = 0u;
    __syncthreads();

    const int p  = tid >> 3;
    const int l8 = tid & 7;
    const int n  = blockIdx.x * SM_PROPS + p;
    const float* row = slog + p * NC;

    float v[11];
    #pragma unroll
    for (int k = 0; k < 10; k++) v[k] = row[l8 + 8 * k];
    v[10] = (l8 == 0) ? row[80] : -INFINITY;

    float mx = v[0];
    #pragma unroll
    for (int k = 1; k < 11; k++) mx = fmaxf(mx, v[k]);
    mx = fmaxf(mx, __shfl_xor_sync(FULLM, mx, 1));
    mx = fmaxf(mx, __shfl_xor_sync(FULLM, mx, 2));
    mx = fmaxf(mx, __shfl_xor_sync(FULLM, mx, 4));

    float e[11];
    float sum = 0.0f;
    #pragma unroll
    for (int k = 0; k < 11; k++) { e[k] = expf(v[k] - mx); sum += e[k]; }
    sum += __shfl_xor_sync(FULLM, sum, 1);
    sum += __shfl_xor_sync(FULLM, sum, 2);
    sum += __shfl_xor_sync(FULLM, sum, 4);

    #pragma unroll
    for (int k = 0; k < 11; k++) {
        int cls = l8 + 8 * k;
        if (cls >= 1 && cls < NC) {
            float sc = e[k] / sum;
            if (sc >= SCORE_T) {
                int cc = cls - 1;
                int pos = atomicAdd(&g_count[cc], 1);
                g_cn[cc * NPROP + pos] = n;
                g_cs[cc * NPROP + pos] = sc;
            }
        }
    }
}

// ---------------------------------------------------------------------------
// Box decode (Fast R-CNN BoxCoder + clip to image)
// ---------------------------------------------------------------------------
__device__ __forceinline__ float4 decode_box(float4 p, float4 d, float W, float H) {
    float w  = p.z - p.x;
    float h  = p.w - p.y;
    float cx = p.x + 0.5f * w;
    float cy = p.y + 0.5f * h;
    float dx = d.x / 10.0f;
    float dy = d.y / 10.0f;
    float dw = fminf(d.z / 5.0f, BBOX_CLIP);
    float dh = fminf(d.w / 5.0f, BBOX_CLIP);
    float pcx = dx * w + cx;
    float pcy = dy * h + cy;
    float pw  = expf(dw) * w;
    float ph  = expf(dh) * h;
    float x1 = fminf(fmaxf(pcx - 0.5f * pw, 0.0f), W);
    float y1 = fminf(fmaxf(pcy - 0.5f * ph, 0.0f), H);
    float x2 = fminf(fmaxf(pcx + 0.5f * pw, 0.0f), W);
    float y2 = fminf(fmaxf(pcy + 0.5f * ph, 0.0f), H);
    return make_float4(x1, y1, x2, y2);
}

__device__ __forceinline__ void img_dims(const int* imh, const int* imw,
                                         float& W, float& H) {
    W = 1216.0f; H = 800.0f;
    if (imw) {
        int vw = *imw, vh = *imh;
        W = (vw > 0 && vw < 100000) ? (float)vw : __int_as_float(vw);
        H = (vh > 0 && vh < 100000) ? (float)vh : __int_as_float(vh);
    }
}

// ---------------------------------------------------------------------------
// Kernel 2: mask build. 320 plain CTAs (4 per class). Decode survivors into
// smem (duplicated x4), then each CTA covers a quarter of the triangular
// pairs; only IoU>thresh bits are REDG.or'd into g_mask.
// ---------------------------------------------------------------------------
__global__ void __launch_bounds__(TN, 1)
mask_kernel(const float* __restrict__ proposal,
            const float* __restrict__ regs,
            const int* __restrict__ imh,
            const int* __restrict__ imw) {
    __shared__ float4 sbox[CAP];
    __shared__ unsigned long long skey[CAP];

    const int bid = blockIdx.x;
    const int tid = threadIdx.x;
    const int c   = bid >> 2;
    const int q   = bid & 3;

    int M = g_count[c];                 // NOT reset here (K3 resets)
    if (M > CAP) M = CAP;

    float W, H;
    img_dims(imh, imw, W, H);

    const float4* prop4 = (const float4*)proposal;
    const float4* reg4  = (const float4*)regs;     // row n = 81 float4 deltas

    for (int i = tid; i < M; i += TN) {
        int   n = g_cn[c * NPROP + i];
        float s = g_cs[c * NPROP + i];
        float4 b = decode_box(prop4[n], reg4[(size_t)n * NC + (c + 1)], W, H);
        bool keep = ((b.z - b.x) >= 1.0f) && ((b.w - b.y) >= 1.0f);
        sbox[i] = b;
        unsigned hi = keep ? __float_as_uint(s) : 0u;
        skey[i] = ((unsigned long long)hi << 32)
                | (unsigned long long)(0xFFFFFFFFu - (unsigned)n);  // ties: smaller n
    }
    __syncthreads();

    long long npairs = (long long)M * (M - 1) / 2;
    const int TT = SPLIT * TN;                     // 1024 lanes per class
    int gt = q * TN + tid;
    long long p0 = npairs * gt / TT;
    long long p1 = npairs * (gt + 1) / TT;
    if (p0 >= p1) return;

    int j = (int)((1.0f + sqrtf((float)(8.0 * (double)p0 + 1.0))) * 0.5f);
    while ((long long)j * (j - 1) / 2 > p0) j--;
    while ((long long)(j + 1) * j / 2 <= p0) j++;
    int i = (int)(p0 - (long long)j * (j - 1) / 2);

    unsigned* gmc = g_mask + (size_t)c * CAP * NW32;
    unsigned long long kj = skey[j];
    float4 bj = sbox[j];
    float  aj = (bj.z - bj.x) * (bj.w - bj.y);
    for (long long p = p0; p < p1; p++) {
        unsigned long long ki = skey[i];
        float4 bi = sbox[i];
        float  ai = (bi.z - bi.x) * (bi.w - bi.y);
        float lx = fmaxf(bi.x, bj.x);
        float ly = fmaxf(bi.y, bj.y);
        float rx = fminf(bi.z, bj.z);
        float ry = fminf(bi.w, bj.w);
        float iw = fmaxf(rx - lx, 0.0f);
        float ih = fmaxf(ry - ly, 0.0f);
        float inter = iw * ih;
        float iou = inter / (ai + aj - inter + 1e-12f);
        if (iou > NMS_T) {
            int loser  = (kj > ki) ? i : j;
            int winner = (kj > ki) ? j : i;
            atomicOr(&gmc[loser * NW32 + (winner >> 5)],
                     1u << (winner & 31));         // no return -> REDG
        }
        if (++i == j) {
            i = 0; j++;
            kj = skey[j]; bj = sbox[j];
            aj = (bj.z - bj.x) * (bj.w - bj.y);
        }
    }
}

// ---------------------------------------------------------------------------
// Kernel 3: per-class re-decode + mask load + rank scatter + warp greedy scan
// + output. 80 CTAs. Output: boxes[8000*4] | scores[8000] | labels | valid
// ---------------------------------------------------------------------------
__global__ void __launch_bounds__(TN, 1)
scan_kernel(const float* __restrict__ proposal,
            const float* __restrict__ regs,
            const int* __restrict__ imh,
            const int* __restrict__ imw,
            float* __restrict__ out) {
    __shared__ float4 sbox[CAP];
    __shared__ unsigned long long skey[CAP];
    __shared__ unsigned long long smask64[CAP * NW64];   // 18 KB
    __shared__ int sidx[CAP];
    __shared__ int aidx[NDET];
    __shared__ unsigned ascr[NDET];
    __shared__ int shM, shNa;
    __shared__ float4 shB0;
    unsigned* smask32 = (unsigned*)smask64;

    const int c   = blockIdx.x;
    const int tid = threadIdx.x;

    if (tid == 0) {
        int m = g_count[c];
        g_count[c] = 0;                 // reset for next replay
        shM = (m > CAP) ? CAP : m;
    }
    __syncthreads();
    const int M = shM;

    float W, H;
    img_dims(imh, imw, W, H);

    const float4* prop4 = (const float4*)proposal;
    const float4* reg4  = (const float4*)regs;

    // issue scattered decode loads early...
    int n0 = -1; float sc0 = 0.0f; float4 pb0, db0;
    if (tid < M) {
        n0  = g_cn[c * NPROP + tid];
        sc0 = g_cs[c * NPROP + tid];
        pb0 = prop4[n0];
        db0 = reg4[(size_t)n0 * NC + (c + 1)];
    }
    // ...and hide their latency behind the coalesced mask load
    {
        const unsigned* gmc = g_mask + (size_t)c * CAP * NW32;
        for (int w = tid; w < M * NW32; w += TN) smask32[w] = gmc[w];
    }
    if (tid < M) {
        float4 b = decode_box(pb0, db0, W, H);
        bool keep = ((b.z - b.x) >= 1.0f) && ((b.w - b.y) >= 1.0f);
        sbox[tid] = b;
        unsigned hi = keep ? __float_as_uint(sc0) : 0u;
        skey[tid] = ((unsigned long long)hi << 32)
                  | (unsigned long long)(0xFFFFFFFFu - (unsigned)n0);
    }
    for (int i = tid + TN; i < M; i += TN) {       // rare: M > 256
        int   n = g_cn[c * NPROP + i];
        float s = g_cs[c * NPROP + i];
        float4 b = decode_box(prop4[n], reg4[(size_t)n * NC + (c + 1)], W, H);
        bool keep = ((b.z - b.x) >= 1.0f) && ((b.w - b.y) >= 1.0f);
        sbox[i] = b;
        unsigned hi = keep ? __float_as_uint(s) : 0u;
        skey[i] = ((unsigned long long)hi << 32)
                | (unsigned long long)(0xFFFFFFFFu - (unsigned)n);
    }
    if (tid == 0) shB0 = decode_box(prop4[0], reg4[c + 1], W, H);
    __syncthreads();

    // rank scatter: rank(i) = #{j : key_j > key_i}; keys unique -> permutation
    for (int i = tid; i < M; i += TN) {
        unsigned long long ki = skey[i];
        int rk = 0;
        for (int j = 0; j < M; j++) rk += (skey[j] > ki) ? 1 : 0;
        sidx[rk] = i;
    }
    __syncthreads();

    // warp-parallel greedy scan (warp 0)
    if (tid < 32) {
        const int lane = tid;
        unsigned long long a0 = 0, a1 = 0, a2 = 0, a3 = 0, a4 = 0, a5 = 0;
        int na = 0;
        for (int chunk = 0; chunk * 32 < M; chunk++) {
            int r = chunk * 32 + lane;
            bool haveR = (r < M);
            int i = haveR ? sidx[r] : 0;
            unsigned sc = haveR ? (unsigned)(skey[i] >> 32) : 0u;
            bool alive = (sc != 0u);
            const unsigned long long* row = &smask64[i * NW64];
            unsigned long long sup = (row[0] & a0) | (row[1] & a1) | (row[2] & a2)
                                   | (row[3] & a3) | (row[4] & a4) | (row[5] & a5);
            unsigned pend   = __ballot_sync(FULLM, alive && (sup == 0ull));
            unsigned aliveb = __ballot_sync(FULLM, alive);
            while (pend) {
                int l = __ffs(pend) - 1;
                pend &= pend - 1;
                int      istar  = __shfl_sync(FULLM, i,  l);
                unsigned scstar = __shfl_sync(FULLM, sc, l);
                if (lane == l) { aidx[na] = istar; ascr[na] = scstar; }
                na++;
                unsigned long long b = 1ull << (istar & 63);
                int w = istar >> 6;
                a0 |= (w == 0) ? b : 0ull;
                a1 |= (w == 1) ? b : 0ull;
                a2 |= (w == 2) ? b : 0ull;
                a3 |= (w == 3) ? b : 0ull;
                a4 |= (w == 4) ? b : 0ull;
                a5 |= (w == 5) ? b : 0ull;
                if (na == NDET) break;
                unsigned myw = smask32[i * NW32 + (istar >> 5)];
                bool nsup = ((myw >> (istar & 31)) & 1u) != 0u;
                unsigned supb = __ballot_sync(FULLM, nsup);
                pend &= ~supb;
            }
            if (na == NDET || aliveb != FULLM) break;
        }
        if (lane == 0) shNa = na;
    }
    __syncthreads();

    const int obase = c * NDET * 4;
    const int sbase = NFG * NDET * 4;        // 32000
    const int lbase = sbase + NFG * NDET;    // 40000
    const int vbase = lbase + NFG * NDET;    // 48000
    const float label = (float)(c + 1);
    const int na = shNa;

    for (int a = tid; a < na; a += TN) {
        float4 b = sbox[aidx[a]];
        out[obase + a * 4 + 0] = b.x;
        out[obase + a * 4 + 1] = b.y;
        out[obase + a * 4 + 2] = b.z;
        out[obase + a * 4 + 3] = b.w;
        int slot = c * NDET + a;
        out[sbase + slot] = __uint_as_float(ascr[a]);
        out[lbase + slot] = label;
        out[vbase + slot] = 1.0f;
    }
    const float4 b0 = shB0;
    for (int jt = na + tid; jt < NDET; jt += TN) {
        out[obase + jt * 4 + 0] = b0.x;
        out[obase + jt * 4 + 1] = b0.y;
        out[obase + jt * 4 + 2] = b0.z;
        out[obase + jt * 4 + 3] = b0.w;
        int slot = c * NDET + jt;
        out[sbase + slot] = 0.0f;
        out[lbase + slot] = label;
        out[vbase + slot] = 0.0f;
    }
}

extern "C" void kernel_launch(void* const* d_in, const int* in_sizes, int n_in,
                              void* d_out, int out_size) {
    const float* proposal = (const float*)d_in[0];
    const float* logits   = (const float*)d_in[1];
    const float* regs     = (const float*)d_in[2];
    const int*   imh      = (n_in >= 5) ? (const int*)d_in[3] : nullptr;
    const int*   imw      = (n_in >= 5) ? (const int*)d_in[4] : nullptr;

    softmax_kernel<<<NPROP / SM_PROPS, 256>>>(logits);
    mask_kernel<<<NFG * SPLIT, TN>>>(proposal, regs, imh, imw);
    scan_kernel<<<NFG, TN>>>(proposal, regs, imh, imw, (float*)d_out);
}

// round 12
// speedup vs baseline: 1.1283x; 1.1283x over previous
#include <cuda_runtime.h>
#include <math.h>

#define NPROP 8192
#define NC 81
#define NFG 80
#define NDET 100
#define SCORE_T 0.05f
#define NMS_T 0.5f
#define BBOX_CLIP 4.135166556742356f   // log(1000/16)
#define CAP 384                         // max survivors/class (E[M]~235, ~10 sigma)
#define NW64 6                          // 64-bit mask words per row
#define NW32 12                         // 32-bit words per row
#define T2 256
#define CLU 4                           // cluster size (CTAs per class)
#define FULLM 0xffffffffu

// Scratch (no cudaMalloc)
__device__ int   g_count[NFG];          // zero at load; nms resets per replay
__device__ int   g_cn[NFG * NPROP];
__device__ float g_cs[NFG * NPROP];

// ---------------------------------------------------------------------------
// Kernel 1: softmax + score-threshold push. 8 lanes per proposal,
// 32 proposals per block, logits staged through smem via LDG.128.
// ---------------------------------------------------------------------------
#define SM_PROPS 32
__global__ void __launch_bounds__(256, 1)
softmax_kernel(const float* __restrict__ logits) {
    __shared__ float slog[SM_PROPS * NC];          // 10368 B
    const int tid = threadIdx.x;

    const float4* src = (const float4*)(logits + (size_t)blockIdx.x * SM_PROPS * NC);
    float4* dst = (float4*)slog;
    #pragma unroll
    for (int k = 0; k < 3; k++) {
        int idx = tid + k * 256;
        if (idx < (SM_PROPS * NC) / 4) dst[idx] = src[idx];
    }
    __syncthreads();

    const int p  = tid >> 3;
    const int l8 = tid & 7;
    const int n  = blockIdx.x * SM_PROPS + p;
    const float* row = slog + p * NC;

    float v[11];
    #pragma unroll
    for (int k = 0; k < 10; k++) v[k] = row[l8 + 8 * k];
    v[10] = (l8 == 0) ? row[80] : -INFINITY;

    float mx = v[0];
    #pragma unroll
    for (int k = 1; k < 11; k++) mx = fmaxf(mx, v[k]);
    mx = fmaxf(mx, __shfl_xor_sync(FULLM, mx, 1));
    mx = fmaxf(mx, __shfl_xor_sync(FULLM, mx, 2));
    mx = fmaxf(mx, __shfl_xor_sync(FULLM, mx, 4));

    float e[11];
    float sum = 0.0f;
    #pragma unroll
    for (int k = 0; k < 11; k++) { e[k] = expf(v[k] - mx); sum += e[k]; }
    sum += __shfl_xor_sync(FULLM, sum, 1);
    sum += __shfl_xor_sync(FULLM, sum, 2);
    sum += __shfl_xor_sync(FULLM, sum, 4);

    #pragma unroll
    for (int k = 0; k < 11; k++) {
        int cls = l8 + 8 * k;
        if (cls >= 1 && cls < NC) {
            float sc = e[k] / sum;
            if (sc >= SCORE_T) {
                int cc = cls - 1;
                int pos = atomicAdd(&g_count[cc], 1);
                g_cn[cc * NPROP + pos] = n;
                g_cs[cc * NPROP + pos] = sc;
            }
        }
    }
}

// ---------------------------------------------------------------------------
// Box decode (Fast R-CNN BoxCoder + clip to image)
// ---------------------------------------------------------------------------
__device__ __forceinline__ float4 decode_box(float4 p, float4 d, float W, float H) {
    float w  = p.z - p.x;
    float h  = p.w - p.y;
    float cx = p.x + 0.5f * w;
    float cy = p.y + 0.5f * h;
    float dx = d.x / 10.0f;
    float dy = d.y / 10.0f;
    float dw = fminf(d.z / 5.0f, BBOX_CLIP);
    float dh = fminf(d.w / 5.0f, BBOX_CLIP);
    float pcx = dx * w + cx;
    float pcy = dy * h + cy;
    float pw  = expf(dw) * w;
    float ph  = expf(dh) * h;
    float x1 = fminf(fmaxf(pcx - 0.5f * pw, 0.0f), W);
    float y1 = fminf(fmaxf(pcy - 0.5f * ph, 0.0f), H);
    float x2 = fminf(fmaxf(pcx + 0.5f * pw, 0.0f), W);
    float y2 = fminf(fmaxf(pcy + 0.5f * ph, 0.0f), H);
    return make_float4(x1, y1, x2, y2);
}

// OR a bit into cluster-rank-0's shared mask (callable from any rank)
__device__ __forceinline__ void cluster_or32(unsigned* p, unsigned val) {
    unsigned laddr = (unsigned)__cvta_generic_to_shared(p);
    unsigned raddr;
    asm volatile("mapa.shared::cluster.u32 %0, %1, 0;" : "=r"(raddr) : "r"(laddr));
    asm volatile("red.relaxed.cluster.shared::cluster.or.b32 [%0], %1;"
                 :: "r"(raddr), "r"(val) : "memory");
}

// Plain store into cluster-rank-0's shared memory
__device__ __forceinline__ void cluster_st32(int* p, int val) {
    unsigned laddr = (unsigned)__cvta_generic_to_shared(p);
    unsigned raddr;
    asm volatile("mapa.shared::cluster.u32 %0, %1, 0;" : "=r"(raddr) : "r"(laddr));
    asm volatile("st.shared::cluster.u32 [%0], %1;"
                 :: "r"(raddr), "r"(val) : "memory");
}

// ---------------------------------------------------------------------------
// Kernel 2 (PDL secondary, CLU-CTA cluster per class):
//  pre-sync: zero smem mask (overlaps softmax via programmatic launch)
//  post-sync: decode (early loads) -> cluster-split rank scatter ->
//  cluster-split triangular pair mask (DSMEM red.or) -> warp greedy scan ->
//  output. Output: boxes[8000*4] | scores[8000] | labels[8000] | valid[8000]
// ---------------------------------------------------------------------------
__global__ void __launch_bounds__(T2, 1) __cluster_dims__(CLU, 1, 1)
nms_fused(const float* __restrict__ proposal,
          const float* __restrict__ regs,
          const int* __restrict__ imh,
          const int* __restrict__ imw,
          float* __restrict__ out) {
    __shared__ float4 sbox[CAP];
    __shared__ unsigned long long skey[CAP];
    __shared__ unsigned long long smask64[CAP * NW64];   // 18 KB
    __shared__ int sidx[CAP];
    __shared__ int aidx[NDET];
    __shared__ unsigned ascr[NDET];
    __shared__ int shNa;
    __shared__ float4 shB0;
    unsigned* smask32 = (unsigned*)smask64;

    const int c   = blockIdx.x / CLU;
    const int tid = threadIdx.x;
    unsigned crank;
    asm("mov.u32 %0, %%cluster_ctarank;" : "=r"(crank));

    // -------- pre-dependency work: zero the suppression mask --------
    for (int i = tid; i < CAP * NW64; i += T2) smask64[i] = 0ull;

    // wait for softmax kernel results (no-op if launched without PDL)
    cudaGridDependencySynchronize();

    int M = g_count[c];
    if (M > CAP) M = CAP;

    float W = 1216.0f, H = 800.0f;
    if (imw) {
        int vw = *imw, vh = *imh;
        W = (vw > 0 && vw < 100000) ? (float)vw : __int_as_float(vw);
        H = (vh > 0 && vh < 100000) ? (float)vh : __int_as_float(vh);
    }

    const float4* prop4 = (const float4*)proposal;
    const float4* reg4  = (const float4*)regs;       // row n = 81 float4 deltas

    // ---- decode survivors; first TN indices with early-issued loads ----
    int n0 = -1; float sc0 = 0.0f; float4 pb0, db0;
    if (tid < M) {
        n0  = g_cn[c * NPROP + tid];
        sc0 = g_cs[c * NPROP + tid];
        pb0 = prop4[n0];
        db0 = reg4[(size_t)n0 * NC + (c + 1)];
    }
    if (tid < M) {
        float4 b = decode_box(pb0, db0, W, H);
        bool keep = ((b.z - b.x) >= 1.0f) && ((b.w - b.y) >= 1.0f);
        sbox[tid] = b;
        unsigned hi = keep ? __float_as_uint(sc0) : 0u;
        skey[tid] = ((unsigned long long)hi << 32)
                  | (unsigned long long)(0xFFFFFFFFu - (unsigned)n0);
    }
    for (int i = tid + T2; i < M; i += T2) {         // rare: M > 256
        int   n = g_cn[c * NPROP + i];
        float s = g_cs[c * NPROP + i];
        float4 b = decode_box(prop4[n], reg4[(size_t)n * NC + (c + 1)], W, H);
        bool keep = ((b.z - b.x) >= 1.0f) && ((b.w - b.y) >= 1.0f);
        sbox[i] = b;
        unsigned hi = keep ? __float_as_uint(s) : 0u;
        skey[i] = ((unsigned long long)hi << 32)
                | (unsigned long long)(0xFFFFFFFFu - (unsigned)n);
    }
    if (crank == 0 && tid == 0) shB0 = decode_box(prop4[0], reg4[c + 1], W, H);
    __syncthreads();

    // cluster sync #1: masks zeroed + decode done everywhere; count read by all
    asm volatile("barrier.cluster.arrive.aligned;" ::: "memory");
    asm volatile("barrier.cluster.wait.aligned;"   ::: "memory");
    if (crank == 0 && tid == 0) g_count[c] = 0;      // reset for next replay

    // ---- rank scatter, split across cluster: CTA q ranks its M/CLU slice ----
    {
        int s0 = ((int)crank * M) / CLU;
        int s1 = (((int)crank + 1) * M) / CLU;
        int i  = s0 + tid;
        if (i < s1) {
            unsigned long long ki = skey[i];
            int rk = 0;
            for (int j = 0; j < M; j++) rk += (skey[j] > ki) ? 1 : 0;
            cluster_st32(&sidx[rk], i);              // keys unique -> permutation
        }
    }

    // ---- triangular pair mask, split across cluster (CLU*T2 lanes) ----
    {
        long long npairs = (long long)M * (M - 1) / 2;
        const int TT = CLU * T2;                     // 1024 lanes per class
        int gt = (int)crank * T2 + tid;
        long long p0 = npairs * gt / TT;
        long long p1 = npairs * (gt + 1) / TT;
        if (p0 < p1) {
            int j = (int)((1.0f + sqrtf((float)(8.0 * (double)p0 + 1.0))) * 0.5f);
            while ((long long)j * (j - 1) / 2 > p0) j--;
            while ((long long)(j + 1) * j / 2 <= p0) j++;
            int i = (int)(p0 - (long long)j * (j - 1) / 2);

            unsigned long long kj = skey[j];
            float4 bj = sbox[j];
            float  aj = (bj.z - bj.x) * (bj.w - bj.y);
            for (long long p = p0; p < p1; p++) {
                unsigned long long ki = skey[i];
                float4 bi = sbox[i];
                float  ai = (bi.z - bi.x) * (bi.w - bi.y);
                float lx = fmaxf(bi.x, bj.x);
                float ly = fmaxf(bi.y, bj.y);
                float rx = fminf(bi.z, bj.z);
                float ry = fminf(bi.w, bj.w);
                float iw = fmaxf(rx - lx, 0.0f);
                float ih = fmaxf(ry - ly, 0.0f);
                float inter = iw * ih;
                float iou = inter / (ai + aj - inter + 1e-12f);
                if (iou > NMS_T) {
                    int loser  = (kj > ki) ? i : j;
                    int winner = (kj > ki) ? j : i;
                    cluster_or32(&smask32[loser * NW32 + (winner >> 5)],
                                 1u << (winner & 31));
                }
                if (++i == j) {
                    i = 0; j++;
                    kj = skey[j]; bj = sbox[j];
                    aj = (bj.z - bj.x) * (bj.w - bj.y);
                }
            }
        }
    }

    // cluster sync #2: all sidx stores + mask bits landed in rank 0
    asm volatile("barrier.cluster.arrive.aligned;" ::: "memory");
    asm volatile("barrier.cluster.wait.aligned;"   ::: "memory");
    if (crank != 0) return;

    // ---- warp-parallel greedy scan (warp 0 of rank-0 CTA) ----
    if (tid < 32) {
        const int lane = tid;
        unsigned long long a0 = 0, a1 = 0, a2 = 0, a3 = 0, a4 = 0, a5 = 0;
        int na = 0;
        for (int chunk = 0; chunk * 32 < M; chunk++) {
            int r = chunk * 32 + lane;
            bool haveR = (r < M);
            int i = haveR ? sidx[r] : 0;
            unsigned sc = haveR ? (unsigned)(skey[i] >> 32) : 0u;
            bool alive = (sc != 0u);
            const unsigned long long* row = &smask64[i * NW64];
            unsigned long long sup = (row[0] & a0) | (row[1] & a1) | (row[2] & a2)
                                   | (row[3] & a3) | (row[4] & a4) | (row[5] & a5);
            unsigned pend   = __ballot_sync(FULLM, alive && (sup == 0ull));
            unsigned aliveb = __ballot_sync(FULLM, alive);
            while (pend) {
                int l = __ffs(pend) - 1;
                pend &= pend - 1;
                int      istar  = __shfl_sync(FULLM, i,  l);
                unsigned scstar = __shfl_sync(FULLM, sc, l);
                if (lane == l) { aidx[na] = istar; ascr[na] = scstar; }
                na++;
                unsigned long long b = 1ull << (istar & 63);
                int w = istar >> 6;
                a0 |= (w == 0) ? b : 0ull;
                a1 |= (w == 1) ? b : 0ull;
                a2 |= (w == 2) ? b : 0ull;
                a3 |= (w == 3) ? b : 0ull;
                a4 |= (w == 4) ? b : 0ull;
                a5 |= (w == 5) ? b : 0ull;
                if (na == NDET) break;
                unsigned myw = smask32[i * NW32 + (istar >> 5)];
                bool nsup = ((myw >> (istar & 31)) & 1u) != 0u;
                unsigned supb = __ballot_sync(FULLM, nsup);
                pend &= ~supb;
            }
            if (na == NDET || aliveb != FULLM) break;
        }
        if (lane == 0) shNa = na;
    }
    __syncthreads();

    // ---- parallel output ----
    const int obase = c * NDET * 4;
    const int sbase = NFG * NDET * 4;        // 32000
    const int lbase = sbase + NFG * NDET;    // 40000
    const int vbase = lbase + NFG * NDET;    // 48000
    const float label = (float)(c + 1);
    const int na = shNa;

    for (int a = tid; a < na; a += T2) {
        float4 b = sbox[aidx[a]];
        out[obase + a * 4 + 0] = b.x;
        out[obase + a * 4 + 1] = b.y;
        out[obase + a * 4 + 2] = b.z;
        out[obase + a * 4 + 3] = b.w;
        int slot = c * NDET + a;
        out[sbase + slot] = __uint_as_float(ascr[a]);
        out[lbase + slot] = label;
        out[vbase + slot] = 1.0f;
    }
    const float4 b0 = shB0;
    for (int jt = na + tid; jt < NDET; jt += T2) {
        out[obase + jt * 4 + 0] = b0.x;
        out[obase + jt * 4 + 1] = b0.y;
        out[obase + jt * 4 + 2] = b0.z;
        out[obase + jt * 4 + 3] = b0.w;
        int slot = c * NDET + jt;
        out[sbase + slot] = 0.0f;
        out[lbase + slot] = label;
        out[vbase + slot] = 0.0f;
    }
}

extern "C" void kernel_launch(void* const* d_in, const int* in_sizes, int n_in,
                              void* d_out, int out_size) {
    const float* proposal = (const float*)d_in[0];
    const float* logits   = (const float*)d_in[1];
    const float* regs     = (const float*)d_in[2];
    const int*   imh      = (n_in >= 5) ? (const int*)d_in[3] : nullptr;
    const int*   imw      = (n_in >= 5) ? (const int*)d_in[4] : nullptr;
    float* outf = (float*)d_out;

    softmax_kernel<<<NPROP / SM_PROPS, 256>>>(logits);

    // PDL launch: nms ramps up while softmax still runs; its
    // cudaGridDependencySynchronize() gates the data-dependent part.
    cudaLaunchConfig_t cfg = {};
    cfg.gridDim  = dim3(NFG * CLU, 1, 1);
    cfg.blockDim = dim3(T2, 1, 1);
    cudaLaunchAttribute attrs[1];
    attrs[0].id = cudaLaunchAttributeProgrammaticStreamSerialization;
    attrs[0].val.programmaticStreamSerializationAllowed = 1;
    cfg.attrs = attrs;
    cfg.numAttrs = 1;
    cudaError_t err = cudaLaunchKernelEx(&cfg, nms_fused,
                                         proposal, regs, imh, imw, outf);
    if (err != cudaSuccess) {
        // fallback: plain launch (gridDependencySync is then a no-op)
        nms_fused<<<NFG * CLU, T2>>>(proposal, regs, imh, imw, outf);
    }
}